// round 6
// baseline (speedup 1.0000x reference)
#include <cuda_runtime.h>
#include <cuda_fp16.h>
#include <stdint.h>

#define NT 4
#define P0 100
#define P1C 100
#define P2C 100

// Scratch: W12[t][i1][i2][m=q1*4+q2][r1] in fp16 (512 halves = 1KB per slice).
// 4*100*100*512 halves = 41 MB -> fully L2-resident.
__device__ __half g_W12[(size_t)NT * P1C * P2C * 512];

// ---- Blackwell packed fp32 helpers -----------------------------------------
#define FMA_F32X2(d, a, b, c) \
    asm("fma.rn.f32x2 %0, %1, %2, %3;" : "=l"(d) : "l"(a), "l"(b), "l"(c))
#define ADD_F32X2_(d, a, b) \
    asm("add.rn.f32x2 %0, %1, %2;" : "=l"(d) : "l"(a), "l"(b))

__device__ __forceinline__ unsigned long long pack2(float lo, float hi) {
    unsigned long long r;
    asm("mov.b64 %0, {%1, %2};" : "=l"(r) : "f"(lo), "f"(hi));
    return r;
}
__device__ __forceinline__ float2 unpack2(unsigned long long v) {
    float2 f;
    asm("mov.b64 {%0, %1}, %2;" : "=f"(f.x), "=f"(f.y) : "l"(v));
    return f;
}

// ---------------------------------------------------------------------------
// Kernel 1: W12[m][r1] = sum_r2 c1[r1][q1][r2] * c2[r2][q2], fp16 output.
// Grid 800 = (t, i1, i2-half). 512 threads: thread = (m=tid>>5, r1=tid&31).
// c1 row hoisted+packed into registers once; half c2 table transposed in smem
// once (no per-i2 barriers). Inner loop: 8 LDS.128 + 16 FFMA2 + 1 STG.16.
// ---------------------------------------------------------------------------
__global__ __launch_bounds__(512) void tt_precompute_kernel(
        const float* __restrict__ c1g, const float* __restrict__ c2g) {
    int b = blockIdx.x;                        // 0..799
    int t  = b / (P1C * 2);
    int rm = b - t * (P1C * 2);
    int i1 = rm >> 1;
    int i2lo = (rm & 1) * 50;

    __shared__ float c2t[50 * 4 * 32];         // [i2'][q2][r2], 25.6KB

    int tid = threadIdx.x;
    int r1 = tid & 31;
    int mA = tid >> 5;                          // 0..15 == m
    int q1 = mA >> 2, q2 = mA & 3;

    // Hoist this thread's c1 row (32 floats) and pack adjacent-r2 pairs.
    const float* c1 = c1g + (size_t)(t * P1C + i1) * 4096;   // [r1][q1][r2]
    const float4* row = (const float4*)(c1 + (r1 * 4 + q1) * 32);
    unsigned long long PA[16];
    #pragma unroll
    for (int k = 0; k < 8; k++) {
        float4 a = row[k];
        PA[2 * k]     = pack2(a.x, a.y);
        PA[2 * k + 1] = pack2(a.z, a.w);
    }

    // Fill smem with transposed c2 half-table: c2t[i2'][q2][r2] = c2[i2][r2][q2]
    const float* c2base = c2g + ((size_t)t * P2C + i2lo) * 128;
    for (int idx = tid; idx < 50 * 128; idx += 512) {
        int i2p = idx >> 7;
        int rr  = (idx >> 2) & 31;
        int qq  = idx & 3;
        c2t[(i2p * 4 + qq) * 32 + rr] = c2base[idx];
    }
    __syncthreads();

    __half* Wt = g_W12 + ((size_t)(t * P1C + i1) * P2C + i2lo) * 512;

    for (int i2p = 0; i2p < 50; i2p++) {
        const ulonglong2* sp = (const ulonglong2*)(c2t + (i2p * 4 + q2) * 32);
        unsigned long long ac0 = 0ULL, ac1 = 0ULL;   // two f32x2 chains
        #pragma unroll
        for (int k = 0; k < 8; k++) {
            ulonglong2 s = sp[k];                    // pairs (r2=4k,4k+1),(4k+2,4k+3)
            FMA_F32X2(ac0, PA[2 * k],     s.x, ac0);
            FMA_F32X2(ac1, PA[2 * k + 1], s.y, ac1);
        }
        float2 f0 = unpack2(ac0), f1 = unpack2(ac1);
        float v = (f0.x + f0.y) + (f1.x + f1.y);
        Wt[i2p * 512 + mA * 32 + r1] = __float2half_rn(v);
    }
}

// ---------------------------------------------------------------------------
// Kernel 2: per-bag lookup + pool. One warp per bag.
// Lane l: j2 = l&3 (r1 chunk of 8), mlow = l>>2; round r gives m = 8r+mlow.
// W slice (1KB fp16) read with 2 coalesced LDG.128/lane; c0 pairs load as
// ulonglong2 (free f32x2 packing); 32 FFMA2 per lookup.
// ---------------------------------------------------------------------------
__global__ void tt_lookup_kernel(const int* __restrict__ indices,
                                 const int* __restrict__ offsets,
                                 const float* __restrict__ c0g,
                                 float* __restrict__ out,
                                 int B, int bags_per_table) {
    int bag = (int)((blockIdx.x * (size_t)blockDim.x + threadIdx.x) >> 5);
    if (bag >= B) return;
    int l = threadIdx.x & 31;
    int j2   = l & 3;
    int mlow = l >> 2;

    int t = bag / bags_per_table;
    int s = offsets[bag], e = offsets[bag + 1];

    const float*  c0tab = c0g + (size_t)t * P0 * 128;            // [i0][q0][r1]
    const __half* Wtab  = g_W12 + (size_t)t * P1C * P2C * 512;

    unsigned long long acc[2][4];                                // f32x2 [r][q0]
    #pragma unroll
    for (int r = 0; r < 2; r++)
        #pragma unroll
        for (int q = 0; q < 4; q++) acc[r][q] = 0ULL;

    for (int base = s; base < e; base += 32) {
        int n = min(32, e - base);
        int myidx = (base + l < e) ? indices[base + l] : 0;      // coalesced
        for (int p = 0; p < n; p++) {
            int idx = __shfl_sync(0xffffffffu, myidx, p);
            int i0  = idx / (P1C * P2C);
            int rem = idx - i0 * (P1C * P2C);
            int i1  = rem / P2C;
            int i2  = rem - i1 * P2C;

            const uint4* wb = (const uint4*)(Wtab + (size_t)(i1 * P2C + i2) * 512);
            const ulonglong2* cb = (const ulonglong2*)(c0tab + i0 * 128);

            // c0 pairs for this lane's 8-wide r1 chunk, all 4 q0.
            ulonglong2 cp[4][2];
            #pragma unroll
            for (int q = 0; q < 4; q++) {
                cp[q][0] = cb[q * 8 + j2 * 2];       // r1 pairs (8j2,+1),(+2,+3)
                cp[q][1] = cb[q * 8 + j2 * 2 + 1];   // r1 pairs (+4,+5),(+6,+7)
            }

            #pragma unroll
            for (int r = 0; r < 2; r++) {
                uint4 u = wb[r * 32 + l];            // 8 halves, coalesced 512B
                const __half2* h = (const __half2*)&u;
                unsigned long long wp[4];
                #pragma unroll
                for (int i = 0; i < 4; i++) {
                    float2 f = __half22float2(h[i]);
                    wp[i] = pack2(f.x, f.y);
                }
                #pragma unroll
                for (int q = 0; q < 4; q++) {
                    FMA_F32X2(acc[r][q], wp[0], cp[q][0].x, acc[r][q]);
                    FMA_F32X2(acc[r][q], wp[1], cp[q][0].y, acc[r][q]);
                    FMA_F32X2(acc[r][q], wp[2], cp[q][1].x, acc[r][q]);
                    FMA_F32X2(acc[r][q], wp[3], cp[q][1].y, acc[r][q]);
                }
            }
        }
    }

    // Reduce r1 partials across the 4 lanes of each (mlow) group.
    #pragma unroll
    for (int r = 0; r < 2; r++)
        #pragma unroll
        for (int q = 0; q < 4; q++) {
            unsigned long long o;
            o = __shfl_xor_sync(0xffffffffu, acc[r][q], 1);
            ADD_F32X2_(acc[r][q], acc[r][q], o);
            o = __shfl_xor_sync(0xffffffffu, acc[r][q], 2);
            ADD_F32X2_(acc[r][q], acc[r][q], o);
        }

    // Lane writes q0 == j2 for both r: out[bag][q0*16 + m], m = 8r + mlow.
    float* ob = out + (size_t)bag * 64;
    #pragma unroll
    for (int q = 0; q < 4; q++) {
        if (q == j2) {
            float2 f0 = unpack2(acc[0][q]);
            float2 f1 = unpack2(acc[1][q]);
            ob[q * 16 + mlow]     = f0.x + f0.y;
            ob[q * 16 + 8 + mlow] = f1.x + f1.y;
        }
    }
}

// ---------------------------------------------------------------------------
extern "C" void kernel_launch(void* const* d_in, const int* in_sizes, int n_in,
                              void* d_out, int out_size) {
    const int* indices = (const int*)d_in[0];
    const int* offsets = (const int*)d_in[1];
    const float* c0 = (const float*)d_in[2];
    const float* c1 = (const float*)d_in[3];
    const float* c2 = (const float*)d_in[4];

    int B = in_sizes[1] - 1;
    int bags_per_table = B / NT;

    tt_precompute_kernel<<<NT * P1C * 2, 512>>>(c1, c2);

    const int warps_per_block = 8;
    int blocks = (B + warps_per_block - 1) / warps_per_block;
    tt_lookup_kernel<<<blocks, warps_per_block * 32>>>(
        indices, offsets, c0, (float*)d_out, B, bags_per_table);
}

// round 7
// speedup vs baseline: 1.6734x; 1.6734x over previous
#include <cuda_runtime.h>
#include <cuda_fp16.h>
#include <stdint.h>

#define NT 4
#define P0 100
#define P1C 100
#define P2C 100

// W12 scratch, stored per (t,i1,i2) slice as TWO mma.m16n8k16 A-fragments
// (k = r1 0..15 and 16..31). Slice = 1KB: frag f at byte f*512, lane l owns
// 16B at l*16 holding regs {a0,a1,a2,a3}. 41 MB total -> L2-resident.
__device__ __align__(16) __half g_W12[(size_t)NT * P1C * P2C * 512];

// c0 as fp16 B-fragments: per (t,i0) slice, lane l holds uint4
// {b0_f0, b1_f0, b0_f1, b1_f1}. B[k=r1][n=q0], cols 4..7 zero. 204.8KB.
__device__ uint4 g_c0f[(size_t)NT * P0 * 32];

// ---- Blackwell packed fp32 helpers -----------------------------------------
#define FMA_F32X2(d, a, b, c) \
    asm("fma.rn.f32x2 %0, %1, %2, %3;" : "=l"(d) : "l"(a), "l"(b), "l"(c))

__device__ __forceinline__ unsigned long long pack2(float lo, float hi) {
    unsigned long long r;
    asm("mov.b64 %0, {%1, %2};" : "=l"(r) : "f"(lo), "f"(hi));
    return r;
}
__device__ __forceinline__ float2 unpack2(unsigned long long v) {
    float2 f;
    asm("mov.b64 {%0, %1}, %2;" : "=f"(f.x), "=f"(f.y) : "l"(v));
    return f;
}
// r = {hi:lo} packed fp16x2
__device__ __forceinline__ unsigned pack_h2(float lo, float hi) {
    unsigned r;
    asm("cvt.rn.f16x2.f32 %0, %1, %2;" : "=r"(r) : "f"(hi), "f"(lo));
    return r;
}

// ---------------------------------------------------------------------------
// Kernel 1: W12[m][r1] = sum_r2 c1[r1][q1][r2] * c2[r2][q2], written in
// A-fragment layout. Block = (t, i1, i2-half), 256 threads = (m, r1-pair kp).
// Thread computes W[m][2kp], W[m][2kp+1] -> exactly one .b32 A-reg (half2).
// c1 rows hoisted+packed in regs once; c2 half-table transposed in smem once.
// ---------------------------------------------------------------------------
__global__ __launch_bounds__(256) void tt_precompute_kernel(
        const float* __restrict__ c1g, const float* __restrict__ c2g) {
    int b = blockIdx.x;                        // 0..799
    int t  = b / (P1C * 2);
    int rm = b - t * (P1C * 2);
    int i1 = rm >> 1;
    int i2lo = (rm & 1) * 50;

    __shared__ __align__(16) float c2t[50 * 128];   // [i2'][q2][r2] 25.6KB

    int tid = threadIdx.x;
    int m  = tid >> 4;                          // 0..15
    int kp = tid & 15;                          // r1 pair: r1 = 2kp, 2kp+1
    int q1 = m >> 2, q2 = m & 3;

    // Hoist + pack this thread's two c1 rows (r1=2kp and 2kp+1).
    const float* c1 = c1g + (size_t)(t * P1C + i1) * 4096;   // [r1][q1][r2]
    const float4* rA = (const float4*)(c1 + (2 * kp * 4 + q1) * 32);
    const float4* rB = (const float4*)(c1 + ((2 * kp + 1) * 4 + q1) * 32);
    unsigned long long PA[8][2], PB[8][2];
    #pragma unroll
    for (int k = 0; k < 8; k++) {
        float4 a = rA[k]; PA[k][0] = pack2(a.x, a.y); PA[k][1] = pack2(a.z, a.w);
        float4 c = rB[k]; PB[k][0] = pack2(c.x, c.y); PB[k][1] = pack2(c.z, c.w);
    }

    // Transposed c2 half-table: c2t[i2'][q2][r2] = c2[i2lo+i2'][r2][q2]
    const float* c2base = c2g + ((size_t)t * P2C + i2lo) * 128;
    for (int idx = tid; idx < 50 * 128; idx += 256) {
        int i2p = idx >> 7;
        int rr  = (idx >> 2) & 31;
        int qq  = idx & 3;
        c2t[i2p * 128 + qq * 32 + rr] = c2base[idx];
    }
    __syncthreads();

    // Fragment-layout destination for this thread's half2:
    // frag = kp>>3; lane = (m&7)*4 + (kp&3); reg = (m>=8) + 2*((kp>>2)&1)
    int frag   = kp >> 3;
    int lane16 = (m & 7) * 4 + (kp & 3);
    int reg    = ((m >> 3) & 1) + (((kp >> 2) & 1) << 1);
    unsigned soff = frag * 512 + lane16 * 16 + reg * 4;
    char* Wt = (char*)g_W12 + ((size_t)(t * P1C + i1) * P2C + i2lo) * 1024;

    for (int i2p = 0; i2p < 50; i2p++) {
        const ulonglong2* sp = (const ulonglong2*)(c2t + i2p * 128 + q2 * 32);
        unsigned long long a0 = 0, a1 = 0, b0 = 0, b1 = 0;
        #pragma unroll
        for (int k = 0; k < 8; k++) {
            ulonglong2 s = sp[k];
            FMA_F32X2(a0, PA[k][0], s.x, a0);
            FMA_F32X2(a1, PA[k][1], s.y, a1);
            FMA_F32X2(b0, PB[k][0], s.x, b0);
            FMA_F32X2(b1, PB[k][1], s.y, b1);
        }
        float2 f0 = unpack2(a0), f1 = unpack2(a1);
        float2 f2 = unpack2(b0), f3 = unpack2(b1);
        float vlo = (f0.x + f0.y) + (f1.x + f1.y);   // W[m][2kp]
        float vhi = (f2.x + f2.y) + (f3.x + f3.y);   // W[m][2kp+1]
        *(unsigned*)(Wt + i2p * 1024 + soff) = pack_h2(vlo, vhi);
    }
}

// ---------------------------------------------------------------------------
// Kernel 1b: c0 -> fp16 B-fragments. One warp per (t,i0) slice.
// b0_f0={B[2j][g],B[2j+1][g]} with B[k][n]=c0[n][k]; cols n=g>=4 are zero.
// ---------------------------------------------------------------------------
__global__ void tt_c0frag_kernel(const float* __restrict__ c0g) {
    int slice = blockIdx.x * (blockDim.x >> 5) + (threadIdx.x >> 5);
    if (slice >= NT * P0) return;
    int lane = threadIdx.x & 31;
    int g = lane >> 2, j = lane & 3;
    uint4 v = make_uint4(0u, 0u, 0u, 0u);
    if (g < 4) {
        const float* row = c0g + (size_t)slice * 128 + g * 32 + 2 * j;
        float2 p0 = *(const float2*)(row);
        float2 p1 = *(const float2*)(row + 8);
        float2 p2 = *(const float2*)(row + 16);
        float2 p3 = *(const float2*)(row + 24);
        v.x = pack_h2(p0.x, p0.y);   // k = 2j, 2j+1
        v.y = pack_h2(p1.x, p1.y);   // k = 2j+8, 2j+9
        v.z = pack_h2(p2.x, p2.y);   // k = 16+2j, ...
        v.w = pack_h2(p3.x, p3.y);   // k = 24+2j, ...
    }
    g_c0f[(size_t)slice * 32 + lane] = v;
}

// ---------------------------------------------------------------------------
// Kernel 2: per-bag lookup + pool via HMMA. One warp per bag.
// Per lookup: 2 shfl + 3 coalesced LDG.128 + 2 mma.m16n8k16 (f32 accum).
// ---------------------------------------------------------------------------
__global__ void tt_lookup_kernel(const int* __restrict__ indices,
                                 const int* __restrict__ offsets,
                                 float* __restrict__ out,
                                 int B, int bags_per_table) {
    int bag = (int)((blockIdx.x * (size_t)blockDim.x + threadIdx.x) >> 5);
    if (bag >= B) return;
    int lane = threadIdx.x & 31;
    int g = lane >> 2, j = lane & 3;

    int t = bag / bags_per_table;
    int s = offsets[bag], e = offsets[bag + 1];

    const uint4* Wt = (const uint4*)(g_W12 + (size_t)t * P1C * P2C * 512);
    const uint4* Cf = g_c0f + (size_t)t * P0 * 32;

    float d0 = 0.f, d1 = 0.f, d2 = 0.f, d3 = 0.f;

    for (int base = s; base < e; base += 32) {
        int n = min(32, e - base);
        int idx = (base + lane < e) ? indices[base + lane] : 0;  // coalesced
        int i0  = idx / 10000;
        int rem = idx - i0 * 10000;
        int i1  = rem / 100;
        int i2  = rem - i1 * 100;
        int wo  = (i1 * 100 + i2) * 64;        // uint4 units (1KB slice)
        int co  = i0 * 32;

        for (int p = 0; p < n; p++) {
            int w = __shfl_sync(0xffffffffu, wo, p);
            int c = __shfl_sync(0xffffffffu, co, p);
            uint4 A0 = Wt[w + lane];
            uint4 A1 = Wt[w + 32 + lane];
            uint4 Bf = Cf[c + lane];
            asm volatile(
                "mma.sync.aligned.m16n8k16.row.col.f32.f16.f16.f32 "
                "{%0,%1,%2,%3}, {%4,%5,%6,%7}, {%8,%9}, {%0,%1,%2,%3};"
                : "+f"(d0), "+f"(d1), "+f"(d2), "+f"(d3)
                : "r"(A0.x), "r"(A0.y), "r"(A0.z), "r"(A0.w),
                  "r"(Bf.x), "r"(Bf.y));
            asm volatile(
                "mma.sync.aligned.m16n8k16.row.col.f32.f16.f16.f32 "
                "{%0,%1,%2,%3}, {%4,%5,%6,%7}, {%8,%9}, {%0,%1,%2,%3};"
                : "+f"(d0), "+f"(d1), "+f"(d2), "+f"(d3)
                : "r"(A1.x), "r"(A1.y), "r"(A1.z), "r"(A1.w),
                  "r"(Bf.z), "r"(Bf.w));
        }
    }

    // D[m][q0]: d0=(g,2j) d1=(g,2j+1) d2=(g+8,2j) d3=(g+8,2j+1);
    // out[bag][q0*16 + m]; only cols 0..3 valid -> lanes with j<2 write.
    if (j < 2) {
        float* ob = out + (size_t)bag * 64;
        ob[(2 * j) * 16 + g]         = d0;
        ob[(2 * j + 1) * 16 + g]     = d1;
        ob[(2 * j) * 16 + g + 8]     = d2;
        ob[(2 * j + 1) * 16 + g + 8] = d3;
    }
}

// ---------------------------------------------------------------------------
extern "C" void kernel_launch(void* const* d_in, const int* in_sizes, int n_in,
                              void* d_out, int out_size) {
    const int* indices = (const int*)d_in[0];
    const int* offsets = (const int*)d_in[1];
    const float* c0 = (const float*)d_in[2];
    const float* c1 = (const float*)d_in[3];
    const float* c2 = (const float*)d_in[4];

    int B = in_sizes[1] - 1;
    int bags_per_table = B / NT;

    tt_c0frag_kernel<<<(NT * P0 + 3) / 4, 128>>>(c0);
    tt_precompute_kernel<<<NT * P1C * 2, 256>>>(c1, c2);

    const int warps_per_block = 8;
    int blocks = (B + warps_per_block - 1) / warps_per_block;
    tt_lookup_kernel<<<blocks, warps_per_block * 32>>>(
        indices, offsets, (float*)d_out, B, bags_per_table);
}